// round 1
// baseline (speedup 1.0000x reference)
#include <cuda_runtime.h>
#include <math.h>

// Problem constants
#define TSTEPS 5      // only timesteps 0..4 matter (output reads h2[4])
#define BATCH  128
#define IN0    512
#define HID    1024
#define G4     4096   // 4*HID
#define OUTD   32
#define SPLITK 4

// Scratch (no allocations allowed -> __device__ globals)
__device__ float g_xg0 [TSTEPS * BATCH * G4];   // layer0 input-gate precompute
__device__ float g_xg1 [TSTEPS * BATCH * G4];   // layer1 input-gate precompute
__device__ float g_h1  [TSTEPS * BATCH * HID];  // layer0 hidden sequence
__device__ float g_h   [BATCH * HID];           // current hidden
__device__ float g_c   [BATCH * HID];           // current cell
__device__ float g_part[SPLITK * BATCH * G4];   // split-K partials of h@Whh^T

// ---------------------------------------------------------------------------
// GEMM: C[M,N] = A[M,K] @ W[N,K]^T + b1[n] + b2[n]
// 128x128 tile, 256 threads, 8x8 per thread, K-chunk 8.
// M, K multiples of 128/8 (used with M=640, N=4096, K=512 or 1024).
// ---------------------------------------------------------------------------
__global__ __launch_bounds__(256) void gemm_bias_kernel(
    const float* __restrict__ A, const float* __restrict__ W,
    const float* __restrict__ b1, const float* __restrict__ b2,
    float* __restrict__ C, int N, int K)
{
    __shared__ float As[8][128];
    __shared__ float Ws[8][128];

    const int tid  = threadIdx.x;
    const int row0 = blockIdx.y * 128;
    const int col0 = blockIdx.x * 128;
    const int tx   = tid % 16;
    const int ty   = tid / 16;

    float acc[8][8];
#pragma unroll
    for (int i = 0; i < 8; i++)
#pragma unroll
        for (int j = 0; j < 8; j++) acc[i][j] = 0.f;

    const int lrow = tid >> 1;        // 0..127
    const int lk4  = (tid & 1) * 4;   // 0 or 4

    for (int k0 = 0; k0 < K; k0 += 8) {
        float4 av = *reinterpret_cast<const float4*>(A + (size_t)(row0 + lrow) * K + k0 + lk4);
        float4 wv = *reinterpret_cast<const float4*>(W + (size_t)(col0 + lrow) * K + k0 + lk4);
        __syncthreads();
        As[lk4 + 0][lrow] = av.x; As[lk4 + 1][lrow] = av.y;
        As[lk4 + 2][lrow] = av.z; As[lk4 + 3][lrow] = av.w;
        Ws[lk4 + 0][lrow] = wv.x; Ws[lk4 + 1][lrow] = wv.y;
        Ws[lk4 + 2][lrow] = wv.z; Ws[lk4 + 3][lrow] = wv.w;
        __syncthreads();
#pragma unroll
        for (int k = 0; k < 8; k++) {
            float af[8], wf[8];
#pragma unroll
            for (int i = 0; i < 4; i++) {
                af[i]     = As[k][ty * 4 + i];
                af[4 + i] = As[k][64 + ty * 4 + i];
            }
#pragma unroll
            for (int j = 0; j < 4; j++) {
                wf[j]     = Ws[k][tx * 4 + j];
                wf[4 + j] = Ws[k][64 + tx * 4 + j];
            }
#pragma unroll
            for (int i = 0; i < 8; i++)
#pragma unroll
                for (int j = 0; j < 8; j++)
                    acc[i][j] = fmaf(af[i], wf[j], acc[i][j]);
        }
    }

#pragma unroll
    for (int i = 0; i < 8; i++) {
        int r = row0 + ((i < 4) ? (ty * 4 + i) : (64 + ty * 4 + (i - 4)));
#pragma unroll
        for (int j = 0; j < 8; j++) {
            int c = col0 + ((j < 4) ? (tx * 4 + j) : (64 + tx * 4 + (j - 4)));
            C[(size_t)r * N + c] = acc[i][j] + b1[c] + b2[c];
        }
    }
}

// ---------------------------------------------------------------------------
// Recurrent GEMM (split-K): P[s] += Hprev[B,HID] @ Whh[G4,HID]^T over K-slice s
// 64x64 tile, 64 threads, 8x8 per thread. grid = (G4/64, BATCH/64, SPLITK)
// ---------------------------------------------------------------------------
__global__ __launch_bounds__(64) void step_gemm_kernel(
    const float* __restrict__ Hprev, const float* __restrict__ Whh)
{
    __shared__ float As[8][64];
    __shared__ float Ws[8][64];

    const int tid  = threadIdx.x;   // 0..63
    const int col0 = blockIdx.x * 64;
    const int row0 = blockIdx.y * 64;
    const int ks   = blockIdx.z;
    const int kbeg = ks * (HID / SPLITK);   // 256-wide slice
    const int tx   = tid % 8;
    const int ty   = tid / 8;

    float acc[8][8];
#pragma unroll
    for (int i = 0; i < 8; i++)
#pragma unroll
        for (int j = 0; j < 8; j++) acc[i][j] = 0.f;

    for (int k0 = 0; k0 < HID / SPLITK; k0 += 8) {
        const float* ap = Hprev + (size_t)(row0 + tid) * HID + kbeg + k0;
        const float* wp = Whh   + (size_t)(col0 + tid) * HID + kbeg + k0;
        float4 a0 = *reinterpret_cast<const float4*>(ap);
        float4 a1 = *reinterpret_cast<const float4*>(ap + 4);
        float4 w0 = *reinterpret_cast<const float4*>(wp);
        float4 w1 = *reinterpret_cast<const float4*>(wp + 4);
        __syncthreads();
        As[0][tid] = a0.x; As[1][tid] = a0.y; As[2][tid] = a0.z; As[3][tid] = a0.w;
        As[4][tid] = a1.x; As[5][tid] = a1.y; As[6][tid] = a1.z; As[7][tid] = a1.w;
        Ws[0][tid] = w0.x; Ws[1][tid] = w0.y; Ws[2][tid] = w0.z; Ws[3][tid] = w0.w;
        Ws[4][tid] = w1.x; Ws[5][tid] = w1.y; Ws[6][tid] = w1.z; Ws[7][tid] = w1.w;
        __syncthreads();
#pragma unroll
        for (int k = 0; k < 8; k++) {
            float af[8], wf[8];
#pragma unroll
            for (int i = 0; i < 4; i++) {
                af[i]     = As[k][ty * 4 + i];
                af[4 + i] = As[k][32 + ty * 4 + i];
            }
#pragma unroll
            for (int j = 0; j < 4; j++) {
                wf[j]     = Ws[k][tx * 4 + j];
                wf[4 + j] = Ws[k][32 + tx * 4 + j];
            }
#pragma unroll
            for (int i = 0; i < 8; i++)
#pragma unroll
                for (int j = 0; j < 8; j++)
                    acc[i][j] = fmaf(af[i], wf[j], acc[i][j]);
        }
    }

    float* P = g_part + (size_t)ks * BATCH * G4;
#pragma unroll
    for (int i = 0; i < 8; i++) {
        int r = row0 + ((i < 4) ? (ty * 4 + i) : (32 + ty * 4 + (i - 4)));
#pragma unroll
        for (int j = 0; j < 8; j++) {
            int c = col0 + ((j < 4) ? (tx * 4 + j) : (32 + tx * 4 + (j - 4)));
            P[(size_t)r * G4 + c] = acc[i][j];
        }
    }
}

// ---------------------------------------------------------------------------
// Gate fusion: g = xg[t] (+ sum of split-K partials). PyTorch order i,f,g,o.
//   c = sig(f)*c_prev + sig(i)*tanh(g);  h = sig(o)*tanh(c)
// ---------------------------------------------------------------------------
__device__ __forceinline__ float sigf(float x) { return 1.f / (1.f + expf(-x)); }

__global__ __launch_bounds__(256) void gates_kernel(
    const float* __restrict__ xg,   // [BATCH][G4] slice for this t
    float* __restrict__ hseq,       // optional: store h for sequence (layer 0)
    int first)
{
    int idx = blockIdx.x * blockDim.x + threadIdx.x;  // 0..BATCH*HID-1
    int b = idx / HID;
    int j = idx % HID;
    size_t base = (size_t)b * G4 + j;

    float gi = xg[base];
    float gf = xg[base + HID];
    float gg = xg[base + 2 * HID];
    float go = xg[base + 3 * HID];

    if (!first) {
#pragma unroll
        for (int s = 0; s < SPLITK; s++) {
            const float* P = g_part + (size_t)s * BATCH * G4;
            gi += P[base];
            gf += P[base + HID];
            gg += P[base + 2 * HID];
            go += P[base + 3 * HID];
        }
    }

    float cprev = first ? 0.f : g_c[idx];
    float ct = sigf(gf) * cprev + sigf(gi) * tanhf(gg);
    float ht = sigf(go) * tanhf(ct);
    g_c[idx] = ct;
    g_h[idx] = ht;
    if (hseq) hseq[idx] = ht;
}

// ---------------------------------------------------------------------------
// Head: out[b,o] = dot(h_final[b,:], Wout[o,:]) + bout[o]
// ---------------------------------------------------------------------------
__global__ __launch_bounds__(256) void head_kernel(
    const float* __restrict__ Wout, const float* __restrict__ bout,
    float* __restrict__ out)
{
    __shared__ float hs[HID];
    __shared__ float red[8][32];
    int b = blockIdx.x;
    for (int i = threadIdx.x; i < HID; i += 256) hs[i] = g_h[(size_t)b * HID + i];
    __syncthreads();

    int o     = threadIdx.x % 32;
    int chunk = threadIdx.x / 32;   // 8 chunks of 128
    float s = 0.f;
    const float* wrow = Wout + (size_t)o * HID;
#pragma unroll 4
    for (int k = chunk * 128; k < chunk * 128 + 128; k++)
        s = fmaf(hs[k], wrow[k], s);
    red[chunk][o] = s;
    __syncthreads();

    if (threadIdx.x < 32) {
        float t = 0.f;
#pragma unroll
        for (int ch = 0; ch < 8; ch++) t += red[ch][threadIdx.x];
        out[(size_t)b * OUTD + threadIdx.x] = t + bout[threadIdx.x];
    }
}

// ---------------------------------------------------------------------------
// Host launcher
// ---------------------------------------------------------------------------
extern "C" void kernel_launch(void* const* d_in, const int* in_sizes, int n_in,
                              void* d_out, int out_size)
{
    const float* input = (const float*)d_in[0];
    const float* w_ih0 = (const float*)d_in[1];
    const float* w_hh0 = (const float*)d_in[2];
    const float* b_ih0 = (const float*)d_in[3];
    const float* b_hh0 = (const float*)d_in[4];
    const float* w_ih1 = (const float*)d_in[5];
    const float* w_hh1 = (const float*)d_in[6];
    const float* b_ih1 = (const float*)d_in[7];
    const float* b_hh1 = (const float*)d_in[8];
    const float* w_out = (const float*)d_in[9];
    const float* b_out = (const float*)d_in[10];
    float* out = (float*)d_out;

    float *xg0, *xg1, *h1, *h;
    cudaGetSymbolAddress((void**)&xg0, g_xg0);
    cudaGetSymbolAddress((void**)&xg1, g_xg1);
    cudaGetSymbolAddress((void**)&h1,  g_h1);
    cudaGetSymbolAddress((void**)&h,   g_h);

    // 1) Layer-0 input gates for t=0..4: [640, 4096] = input[0:640,512] @ w_ih0^T + biases
    {
        dim3 grid(G4 / 128, (TSTEPS * BATCH) / 128);
        gemm_bias_kernel<<<grid, 256>>>(input, w_ih0, b_ih0, b_hh0, xg0, G4, IN0);
    }

    // 2) Layer-0 recurrence (5 steps)
    for (int t = 0; t < TSTEPS; t++) {
        if (t > 0) {
            dim3 grid(G4 / 64, BATCH / 64, SPLITK);
            step_gemm_kernel<<<grid, 64>>>(h, w_hh0);
        }
        gates_kernel<<<(BATCH * HID) / 256, 256>>>(
            xg0 + (size_t)t * BATCH * G4, h1 + (size_t)t * BATCH * HID, t == 0 ? 1 : 0);
    }

    // 3) Layer-1 input gates: [640, 4096] = h1 @ w_ih1^T + biases
    {
        dim3 grid(G4 / 128, (TSTEPS * BATCH) / 128);
        gemm_bias_kernel<<<grid, 256>>>(h1, w_ih1, b_ih1, b_hh1, xg1, G4, HID);
    }

    // 4) Layer-1 recurrence (5 steps)
    for (int t = 0; t < TSTEPS; t++) {
        if (t > 0) {
            dim3 grid(G4 / 64, BATCH / 64, SPLITK);
            step_gemm_kernel<<<grid, 64>>>(h, w_hh1);
        }
        gates_kernel<<<(BATCH * HID) / 256, 256>>>(
            xg1 + (size_t)t * BATCH * G4, (float*)0, t == 0 ? 1 : 0);
    }

    // 5) Linear head on h2[4] (current g_h)
    head_kernel<<<BATCH, 256>>>(w_out, b_out, out);
}

// round 3
// speedup vs baseline: 2.2247x; 2.2247x over previous
#include <cuda_runtime.h>
#include <cuda_bf16.h>
#include <math.h>
#include <stdint.h>

#define TSTEPS 5
#define BATCH  128
#define IN0    512
#define HID    1024
#define G4     4096
#define OUTD   32
#define SPLITK 4

#define BM 128
#define BN 128
#define BK 32
#define NTH 256
// SMEM row stride in bf16 elements (32 data + 8 pad -> 80B, conflict-free ldmatrix)
#define RS 40

// Scratch (device globals; no allocations allowed)
__device__ float g_xg0 [TSTEPS * BATCH * G4];
__device__ float g_xg1 [TSTEPS * BATCH * G4];
__device__ float g_h1  [TSTEPS * BATCH * HID];
__device__ float g_h   [BATCH * HID];
__device__ float g_c   [BATCH * HID];
__device__ float g_part[SPLITK * BATCH * G4];

__device__ __forceinline__ uint32_t smem_u32(const void* p) {
    uint32_t a;
    asm("{ .reg .u64 t; cvta.to.shared.u64 t, %1; cvt.u32.u64 %0, t; }"
        : "=r"(a) : "l"(p));
    return a;
}

#define LDSM_X4(R, addr)                                                     \
    asm volatile("ldmatrix.sync.aligned.m8n8.x4.shared.b16 "                 \
                 "{%0,%1,%2,%3}, [%4];"                                      \
                 : "=r"((R)[0]), "=r"((R)[1]), "=r"((R)[2]), "=r"((R)[3])    \
                 : "r"(addr))
#define LDSM_X2(R, addr)                                                     \
    asm volatile("ldmatrix.sync.aligned.m8n8.x2.shared.b16 {%0,%1}, [%2];"   \
                 : "=r"((R)[0]), "=r"((R)[1]) : "r"(addr))
#define MMA_BF16(D, Ar, Br)                                                  \
    asm volatile("mma.sync.aligned.m16n8k16.row.col.f32.bf16.bf16.f32 "      \
                 "{%0,%1,%2,%3}, {%4,%5,%6,%7}, {%8,%9}, {%0,%1,%2,%3};"     \
                 : "+f"((D)[0]), "+f"((D)[1]), "+f"((D)[2]), "+f"((D)[3])    \
                 : "r"((Ar)[0]), "r"((Ar)[1]), "r"((Ar)[2]), "r"((Ar)[3]),   \
                   "r"((Br)[0]), "r"((Br)[1]))

// ---------------------------------------------------------------------------
// Tensor-core GEMM: C[128*gy : , 128*gx :] (+bias) = A[*,K] @ W[N,K]^T
// fp32 in, bf16 hi/lo split (3-term), fp32 accum. blockIdx.z = split-K slice.
// ---------------------------------------------------------------------------
__global__ __launch_bounds__(NTH) void hmma_gemm(
    const float* __restrict__ A, const float* __restrict__ W,
    int strideA, int strideW, int ksize,
    const float* __restrict__ b1, const float* __restrict__ b2,
    float* __restrict__ Cbase, int ldc, int zStride)
{
    __shared__ uint16_t sA[2][BM * RS];   // [hi/lo][row*RS + col]
    __shared__ uint16_t sW[2][BN * RS];

    const int tid  = threadIdx.x;
    const int lane = tid & 31;
    const int warp = tid >> 5;
    const int wm   = warp >> 2;           // 0..1
    const int wn   = warp & 3;            // 0..3
    const int row0 = blockIdx.y * BM;
    const int col0 = blockIdx.x * BN;
    const int kbeg = blockIdx.z * ksize;
    const int nch  = ksize / BK;

    // Prefetch assignment: threads 0-127 -> A tile, 128-255 -> W tile.
    const bool isA = (tid < 128);
    const int  t2  = tid & 127;
    const float* src = isA ? (A + (size_t)row0 * strideA)
                           : (W + (size_t)col0 * strideW);
    const int sstr = isA ? strideA : strideW;
    uint16_t* d0 = isA ? sA[0] : sW[0];
    uint16_t* d1 = isA ? sA[1] : sW[1];

    float4 pf[8];

    // ldmatrix base addresses (byte offsets computed per use)
    const uint32_t bA0 = smem_u32(sA[0]);
    const uint32_t bA1 = smem_u32(sA[1]);
    const uint32_t bW0 = smem_u32(sW[0]);
    const uint32_t bW1 = smem_u32(sW[1]);

    float acc[4][4][4];
#pragma unroll
    for (int i = 0; i < 4; i++)
#pragma unroll
        for (int j = 0; j < 4; j++)
#pragma unroll
            for (int v = 0; v < 4; v++) acc[i][j][v] = 0.f;

    // ---- load chunk 0 into regs ----
#pragma unroll
    for (int i = 0; i < 8; i++) {
        int idx = t2 + 128 * i;           // 0..1023 float4s
        int r = idx >> 3, c4 = idx & 7;
        pf[i] = *(const float4*)(src + (size_t)r * sstr + kbeg + c4 * 4);
    }

    const int rl  = lane & 7;
    const int s8  = (lane >> 3) & 1;
    const int s16 = (lane >> 4) & 1;

    for (int c = 0; c < nch; c++) {
        // store regs -> smem (hi/lo split)
#pragma unroll
        for (int i = 0; i < 8; i++) {
            int idx = t2 + 128 * i;
            int r = idx >> 3, c4 = idx & 7;
            float f[4] = {pf[i].x, pf[i].y, pf[i].z, pf[i].w};
            uint16_t h[4], l[4];
#pragma unroll
            for (int j = 0; j < 4; j++) {
                __nv_bfloat16 hb = __float2bfloat16(f[j]);
                __nv_bfloat16 lb = __float2bfloat16(f[j] - __bfloat162float(hb));
                h[j] = __bfloat16_as_ushort(hb);
                l[j] = __bfloat16_as_ushort(lb);
            }
            int o = r * RS + c4 * 4;
            *(uint2*)(d0 + o) = *(uint2*)h;
            *(uint2*)(d1 + o) = *(uint2*)l;
        }
        __syncthreads();

        // prefetch next chunk (LDG overlaps the MMA stream below)
        if (c + 1 < nch) {
            const int kk = kbeg + (c + 1) * BK;
#pragma unroll
            for (int i = 0; i < 8; i++) {
                int idx = t2 + 128 * i;
                int r = idx >> 3, c4 = idx & 7;
                pf[i] = *(const float4*)(src + (size_t)r * sstr + kk + c4 * 4);
            }
        }

        // compute: 2 k-steps of 16
#pragma unroll
        for (int ks = 0; ks < 2; ks++) {
            const int k0b = (ks * 16 + s8 * 8) * 2;       // byte col offset (B)
            const int k0a = (ks * 16 + s16 * 8) * 2;      // byte col offset (A)

            uint32_t bh[4][2], bl[4][2];
#pragma unroll
            for (int nt = 0; nt < 4; nt++) {
                uint32_t ro = (uint32_t)(wn * 32 + nt * 8 + rl) * (RS * 2) + k0b;
                LDSM_X2(bh[nt], bW0 + ro);
                LDSM_X2(bl[nt], bW1 + ro);
            }
#pragma unroll
            for (int mt = 0; mt < 4; mt++) {
                uint32_t ro = (uint32_t)(wm * 64 + mt * 16 + rl + s8 * 8) * (RS * 2) + k0a;
                uint32_t ah[4], al[4];
                LDSM_X4(ah, bA0 + ro);
                LDSM_X4(al, bA1 + ro);
#pragma unroll
                for (int nt = 0; nt < 4; nt++) {
                    MMA_BF16(acc[mt][nt], ah, bh[nt]);   // hi*hi
                    MMA_BF16(acc[mt][nt], ah, bl[nt]);   // hi*lo
                    MMA_BF16(acc[mt][nt], al, bh[nt]);   // lo*hi
                }
            }
        }
        __syncthreads();
    }

    // Epilogue: direct fragment stores (+bias)
    float* outp = Cbase + (size_t)blockIdx.z * zStride;
#pragma unroll
    for (int mt = 0; mt < 4; mt++) {
        int row = row0 + wm * 64 + mt * 16 + (lane >> 2);
#pragma unroll
        for (int nt = 0; nt < 4; nt++) {
            int col = col0 + wn * 32 + nt * 8 + (lane & 3) * 2;
            float bb0 = 0.f, bb1 = 0.f;
            if (b1) {
                bb0 = b1[col] + b2[col];
                bb1 = b1[col + 1] + b2[col + 1];
            }
            float2 v0 = make_float2(acc[mt][nt][0] + bb0, acc[mt][nt][1] + bb1);
            float2 v1 = make_float2(acc[mt][nt][2] + bb0, acc[mt][nt][3] + bb1);
            *(float2*)(outp + (size_t)row * ldc + col) = v0;
            *(float2*)(outp + (size_t)(row + 8) * ldc + col) = v1;
        }
    }
}

// ---------------------------------------------------------------------------
// Gate fusion (float4): g = xg + sum split-K partials; order i,f,g,o
// ---------------------------------------------------------------------------
__device__ __forceinline__ float sigf(float x) { return 1.f / (1.f + expf(-x)); }

__global__ __launch_bounds__(256) void gates_kernel(
    const float* __restrict__ xg, float* __restrict__ hseq, int first)
{
    int q  = blockIdx.x * blockDim.x + threadIdx.x;
    int b  = q / (HID / 4);
    int j4 = (q % (HID / 4)) * 4;
    size_t base = (size_t)b * G4 + j4;

    float4 gi = *(const float4*)(xg + base);
    float4 gf = *(const float4*)(xg + base + HID);
    float4 gg = *(const float4*)(xg + base + 2 * HID);
    float4 go = *(const float4*)(xg + base + 3 * HID);

    if (!first) {
#pragma unroll
        for (int s = 0; s < SPLITK; s++) {
            const float* P = g_part + (size_t)s * BATCH * G4 + base;
            float4 p;
            p = *(const float4*)(P);           gi.x += p.x; gi.y += p.y; gi.z += p.z; gi.w += p.w;
            p = *(const float4*)(P + HID);     gf.x += p.x; gf.y += p.y; gf.z += p.z; gf.w += p.w;
            p = *(const float4*)(P + 2 * HID); gg.x += p.x; gg.y += p.y; gg.z += p.z; gg.w += p.w;
            p = *(const float4*)(P + 3 * HID); go.x += p.x; go.y += p.y; go.z += p.z; go.w += p.w;
        }
    }

    int idx = b * HID + j4;
    float4 cp = first ? make_float4(0.f, 0.f, 0.f, 0.f) : *(const float4*)(g_c + idx);

    float ci[4] = {gi.x, gi.y, gi.z, gi.w};
    float cf[4] = {gf.x, gf.y, gf.z, gf.w};
    float cg[4] = {gg.x, gg.y, gg.z, gg.w};
    float co[4] = {go.x, go.y, go.z, go.w};
    float cpv[4] = {cp.x, cp.y, cp.z, cp.w};
    float cv[4], hv[4];
#pragma unroll
    for (int j = 0; j < 4; j++) {
        cv[j] = sigf(cf[j]) * cpv[j] + sigf(ci[j]) * tanhf(cg[j]);
        hv[j] = sigf(co[j]) * tanhf(cv[j]);
    }
    *(float4*)(g_c + idx) = make_float4(cv[0], cv[1], cv[2], cv[3]);
    float4 hout = make_float4(hv[0], hv[1], hv[2], hv[3]);
    *(float4*)(g_h + idx) = hout;
    if (hseq) *(float4*)(hseq + idx) = hout;
}

// ---------------------------------------------------------------------------
// Head: out[b,o] = dot(h_final[b,:], Wout[o,:]) + bout[o]
// ---------------------------------------------------------------------------
__global__ __launch_bounds__(256) void head_kernel(
    const float* __restrict__ Wout, const float* __restrict__ bout,
    float* __restrict__ out)
{
    __shared__ float hs[HID];
    __shared__ float red[8][32];
    int b = blockIdx.x;
    for (int i = threadIdx.x; i < HID; i += 256) hs[i] = g_h[(size_t)b * HID + i];
    __syncthreads();

    int o     = threadIdx.x % 32;
    int chunk = threadIdx.x / 32;
    float s = 0.f;
    const float* wrow = Wout + (size_t)o * HID;
#pragma unroll 4
    for (int k = chunk * 128; k < chunk * 128 + 128; k++)
        s = fmaf(hs[k], wrow[k], s);
    red[chunk][o] = s;
    __syncthreads();

    if (threadIdx.x < 32) {
        float t = 0.f;
#pragma unroll
        for (int ch = 0; ch < 8; ch++) t += red[ch][threadIdx.x];
        out[(size_t)b * OUTD + threadIdx.x] = t + bout[threadIdx.x];
    }
}

// ---------------------------------------------------------------------------
// Host launcher
// ---------------------------------------------------------------------------
extern "C" void kernel_launch(void* const* d_in, const int* in_sizes, int n_in,
                              void* d_out, int out_size)
{
    const float* input = (const float*)d_in[0];
    const float* w_ih0 = (const float*)d_in[1];
    const float* w_hh0 = (const float*)d_in[2];
    const float* b_ih0 = (const float*)d_in[3];
    const float* b_hh0 = (const float*)d_in[4];
    const float* w_ih1 = (const float*)d_in[5];
    const float* w_hh1 = (const float*)d_in[6];
    const float* b_ih1 = (const float*)d_in[7];
    const float* b_hh1 = (const float*)d_in[8];
    const float* w_out = (const float*)d_in[9];
    const float* b_out = (const float*)d_in[10];
    float* out = (float*)d_out;

    float *xg0, *xg1, *h1, *h, *part;
    cudaGetSymbolAddress((void**)&xg0,  g_xg0);
    cudaGetSymbolAddress((void**)&xg1,  g_xg1);
    cudaGetSymbolAddress((void**)&h1,   g_h1);
    cudaGetSymbolAddress((void**)&h,    g_h);
    cudaGetSymbolAddress((void**)&part, g_part);

    const int KSLICE = HID / SPLITK;   // 256
    const int ZSTR   = BATCH * G4;

    // 1) Layer-0 input gates: [640,4096] = input[0:640,512] @ w_ih0^T + biases
    {
        dim3 grid(G4 / BN, TSTEPS * BATCH / BM, 1);
        hmma_gemm<<<grid, NTH>>>(input, w_ih0, IN0, IN0, IN0,
                                 b_ih0, b_hh0, xg0, G4, 0);
    }
    // 2) Layer-0 recurrence
    for (int t = 0; t < TSTEPS; t++) {
        if (t > 0) {
            dim3 grid(G4 / BN, 1, SPLITK);
            hmma_gemm<<<grid, NTH>>>(h, w_hh0, HID, HID, KSLICE,
                                     (const float*)0, (const float*)0,
                                     part, G4, ZSTR);
        }
        gates_kernel<<<(BATCH * HID / 4) / 256, 256>>>(
            xg0 + (size_t)t * BATCH * G4, h1 + (size_t)t * BATCH * HID, t == 0);
    }
    // 3) Layer-1 input gates: [640,4096] = h1 @ w_ih1^T + biases
    {
        dim3 grid(G4 / BN, TSTEPS * BATCH / BM, 1);
        hmma_gemm<<<grid, NTH>>>(h1, w_ih1, HID, HID, HID,
                                 b_ih1, b_hh1, xg1, G4, 0);
    }
    // 4) Layer-1 recurrence
    for (int t = 0; t < TSTEPS; t++) {
        if (t > 0) {
            dim3 grid(G4 / BN, 1, SPLITK);
            hmma_gemm<<<grid, NTH>>>(h, w_hh1, HID, HID, KSLICE,
                                     (const float*)0, (const float*)0,
                                     part, G4, ZSTR);
        }
        gates_kernel<<<(BATCH * HID / 4) / 256, 256>>>(
            xg1 + (size_t)t * BATCH * G4, (float*)0, t == 0);
    }
    // 5) Linear head on h2[4]
    head_kernel<<<BATCH, 256>>>(w_out, b_out, out);
}